// round 3
// baseline (speedup 1.0000x reference)
#include <cuda_runtime.h>
#include <cstdint>

// BlockedF8Linear: out[m,n] = sum_k x[m,k] * (w[n,k]*scale[n/128,k/128]) + bias[n]
// M = B*S = 4096, N = OUT = 4096, K = IN = 4096.
//
// Round-3 strategy: single, verified-safe tensor-core path using Ampere-era
// mma.sync.m16n8k8.tf32 (legal from sm_80, compiles under both the compute_103
// PTX pass and the sm_103a SASS pass). Precision: weights are exact e4m3
// values stored as fp32 -> exact in tf32 (10-bit mantissa); only x*scale is
// tf32-rounded (~2.5e-4 aggregate rel err << 1e-3). fp32 accumulation.
//
// CTA tile 128x128, K-chunk 32, 256 threads (8 warps as 2(M) x 4(N), warp tile
// 64x32). Double-buffered SMEM holds tf32 operands in mma-fragment-major
// layout: A: [mtile(8)][kstep(4)][reg(4)][lane(32)] u32 (16 KB),
//         B: [ntile(16)][kstep(4)][reg(2)][lane(32)] u32 (16 KB),
// lane index XOR-swizzled by (k4<<2) so producer STS.128 spreads across banks
// and consumer scalar LDS is conflict-free.

#define KDIM 4096
#define NDIM 4096
#define MDIM 4096

#define FKC 32
#define FNCH (KDIM / FKC)          // 128 K-chunks
#define FA_WORDS 4096
#define FB_WORDS 4096
#define FBUF_WORDS (FA_WORDS + FB_WORDS)
#define FSMEM_BYTES (2 * FBUF_WORDS * 4)   // 65536

static __device__ __forceinline__ uint32_t f2tf32(float f) {
    uint32_t u;
    asm("cvt.rna.tf32.f32 %0, %1;" : "=r"(u) : "f"(f));
    return u;
}

static __device__ __forceinline__ void mma_tf32(float* c, const uint32_t* a,
                                                const uint32_t* b) {
    asm volatile(
        "mma.sync.aligned.m16n8k8.row.col.f32.tf32.tf32.f32 "
        "{%0,%1,%2,%3}, {%4,%5,%6,%7}, {%8,%9}, {%0,%1,%2,%3};"
        : "+f"(c[0]), "+f"(c[1]), "+f"(c[2]), "+f"(c[3])
        : "r"(a[0]), "r"(a[1]), "r"(a[2]), "r"(a[3]), "r"(b[0]), "r"(b[1]));
}

extern "C" __global__ void __launch_bounds__(256)
f8lin_tf32(const float* __restrict__ x, const float* __restrict__ w,
           const float* __restrict__ sinv, const float* __restrict__ bias,
           float* __restrict__ out) {
    extern __shared__ uint32_t fsm[];
    const int tid = threadIdx.x;
    const int warp = tid >> 5;
    const int lane = tid & 31;
    const int wm = warp >> 2;       // 0..1 -> M offset wm*64
    const int wn = warp & 3;        // 0..3 -> N offset wn*32

    const int n0 = blockIdx.x * 128;
    const int m0 = blockIdx.y * 128;

    // producer mapping: thread t covers k4 = t&7 (k-quad), rows rbase + it*32
    const int k4 = tid & 7;
    const int rbase = tid >> 3;     // 0..31
    const int kstepW = k4 >> 1;

    const float* xp = x + (size_t)(m0 + rbase) * KDIM + k4 * 4;
    const float* wp = w + (size_t)(n0 + rbase) * KDIM + k4 * 4;

    // per-it store word offsets (fragment-major + XOR lane swizzle)
    uint32_t aoff[4], boff[4];
#pragma unroll
    for (int it = 0; it < 4; ++it) {
        int m = rbase + it * 32;
        aoff[it] = ((((m >> 4) * 4 + kstepW) * 4 + ((m >> 3) & 1) + 2 * (k4 & 1)) << 5)
                   + (((m & 7) ^ k4) << 2);
        int n = m;
        boff[it] = FA_WORDS
                   + ((((n >> 3) * 4 + kstepW) * 2 + (k4 & 1)) << 5)
                   + (((n & 7) ^ k4) << 2);
    }

    float acc[4][4][4];
#pragma unroll
    for (int i = 0; i < 4; ++i)
#pragma unroll
        for (int j = 0; j < 4; ++j)
#pragma unroll
            for (int r = 0; r < 4; ++r) acc[i][j][r] = 0.0f;

    float4 pax[4], pbx[4];
    float ps;

    // prologue: load + convert + store chunk 0 into buffer 0
    ps = __ldg(sinv + (size_t)blockIdx.x * 32 + 0);
#pragma unroll
    for (int it = 0; it < 4; ++it) {
        pax[it] = *reinterpret_cast<const float4*>(xp + (size_t)it * 32 * KDIM);
        pbx[it] = *reinterpret_cast<const float4*>(wp + (size_t)it * 32 * KDIM);
    }
    {
        uint32_t* buf = fsm;
#pragma unroll
        for (int it = 0; it < 4; ++it) {
            float4 v = pax[it];
            uint4 t;
            t.x = f2tf32(v.x * ps); t.y = f2tf32(v.y * ps);
            t.z = f2tf32(v.z * ps); t.w = f2tf32(v.w * ps);
            *reinterpret_cast<uint4*>(buf + aoff[it]) = t;
            float4 u = pbx[it];
            uint4 s2;
            s2.x = f2tf32(u.x); s2.y = f2tf32(u.y);
            s2.z = f2tf32(u.z); s2.w = f2tf32(u.w);
            *reinterpret_cast<uint4*>(buf + boff[it]) = s2;
        }
    }
    __syncthreads();

#pragma unroll 1
    for (int kc = 0; kc < FNCH; ++kc) {
        // prefetch next chunk from gmem (overlaps with MMA below)
        if (kc + 1 < FNCH) {
            const float* xn = xp + (kc + 1) * FKC;
            const float* wn2 = wp + (kc + 1) * FKC;
            ps = __ldg(sinv + (size_t)blockIdx.x * 32 + ((kc + 1) >> 2));
#pragma unroll
            for (int it = 0; it < 4; ++it) {
                pax[it] = *reinterpret_cast<const float4*>(xn + (size_t)it * 32 * KDIM);
                pbx[it] = *reinterpret_cast<const float4*>(wn2 + (size_t)it * 32 * KDIM);
            }
        }

        // compute on buffer kc&1
        const uint32_t* buf = fsm + (kc & 1) * FBUF_WORDS;
#pragma unroll
        for (int ks = 0; ks < 4; ++ks) {
            uint32_t afr[4][4], bfr[4][2];
#pragma unroll
            for (int mt = 0; mt < 4; ++mt) {
                int mtileC = wm * 4 + mt;
#pragma unroll
                for (int r = 0; r < 4; ++r) {
                    int k4c = ks * 2 + (r >> 1);
                    afr[mt][r] = buf[(((mtileC * 4 + ks) * 4 + r) << 5)
                                     + (lane ^ (k4c << 2))];
                }
            }
#pragma unroll
            for (int nt = 0; nt < 4; ++nt) {
                int ntileC = wn * 4 + nt;
#pragma unroll
                for (int r = 0; r < 2; ++r) {
                    int k4c = ks * 2 + r;
                    bfr[nt][r] = buf[FA_WORDS + (((ntileC * 4 + ks) * 2 + r) << 5)
                                     + (lane ^ (k4c << 2))];
                }
            }
#pragma unroll
            for (int mt = 0; mt < 4; ++mt)
#pragma unroll
                for (int nt = 0; nt < 4; ++nt)
                    mma_tf32(acc[mt][nt], afr[mt], bfr[nt]);
        }

        __syncthreads();
        if (kc + 1 < FNCH) {
            uint32_t* bufw = fsm + ((kc + 1) & 1) * FBUF_WORDS;
#pragma unroll
            for (int it = 0; it < 4; ++it) {
                float4 v = pax[it];
                uint4 t;
                t.x = f2tf32(v.x * ps); t.y = f2tf32(v.y * ps);
                t.z = f2tf32(v.z * ps); t.w = f2tf32(v.w * ps);
                *reinterpret_cast<uint4*>(bufw + aoff[it]) = t;
                float4 u = pbx[it];
                uint4 s2;
                s2.x = f2tf32(u.x); s2.y = f2tf32(u.y);
                s2.z = f2tf32(u.z); s2.w = f2tf32(u.w);
                *reinterpret_cast<uint4*>(bufw + boff[it]) = s2;
            }
            __syncthreads();
        }
    }

    // epilogue: acc + bias -> out (c0/c1 at row, c2/c3 at row+8)
#pragma unroll
    for (int nt = 0; nt < 4; ++nt) {
        int col = n0 + wn * 32 + nt * 8 + (lane & 3) * 2;
        float2 bv = *reinterpret_cast<const float2*>(bias + col);
#pragma unroll
        for (int mt = 0; mt < 4; ++mt) {
            int row = m0 + wm * 64 + mt * 16 + (lane >> 2);
            float2 o0, o1;
            o0.x = acc[mt][nt][0] + bv.x;
            o0.y = acc[mt][nt][1] + bv.y;
            o1.x = acc[mt][nt][2] + bv.x;
            o1.y = acc[mt][nt][3] + bv.y;
            *reinterpret_cast<float2*>(out + (size_t)row * NDIM + col) = o0;
            *reinterpret_cast<float2*>(out + (size_t)(row + 8) * NDIM + col) = o1;
        }
    }
}

extern "C" void kernel_launch(void* const* d_in, const int* in_sizes, int n_in,
                              void* d_out, int out_size) {
    const float* x = (const float*)d_in[0];
    const float* w = (const float*)d_in[1];
    const float* s = (const float*)d_in[2];
    const float* b = (const float*)d_in[3];
    float* out = (float*)d_out;

    cudaFuncSetAttribute(f8lin_tf32,
                         cudaFuncAttributeMaxDynamicSharedMemorySize, FSMEM_BYTES);
    // x fastest over N-tiles: a wave shares the x slab and W stays hot in L2
    dim3 grid(NDIM / 128, MDIM / 128);
    f8lin_tf32<<<grid, 256, FSMEM_BYTES>>>(x, w, s, b, out);
}